// round 8
// baseline (speedup 1.0000x reference)
#include <cuda_runtime.h>
#include <cstdint>

// ExpandMask: x [B=64, 1, L=262144] f32 -> out [B, 1, 2L] float (0.0/1.0)
//   out[2i]   = (x[i-1] + x[i] + x[i+1] > 0.5)   (zero taps outside row)
//   out[2i+1] = (x[i]   + x[i+1]        > 0.5)
//
// R8: R5 coalesced mapping (one output float4 per lane per chunk, dense
// LDG.64 + dense STG.128, shuffle halos, CHUNKS=4). Store policy changed to
// write-through (__stwt): stores leave NO resident L2 line, so the 64MB
// input (default-cached loads) can stay L2-resident across graph replays.
// Steady state target: DRAM carries the 128MB write stream only.

static constexpr int L = 262144;                    // input row length
static constexpr int OUT_F4_PER_ROW = (2 * L) / 4;  // 131072 = 2^17
static constexpr int CHUNKS = 4;
static constexpr int BLOCK = 256;

__global__ void __launch_bounds__(BLOCK) expand_mask_kernel(
    const float* __restrict__ x, float4* __restrict__ out)
{
    const int lane = threadIdx.x & 31;
    const int block_base = blockIdx.x * (BLOCK * CHUNKS);

    // Front-batch 4 independent dense float2 loads (MLP = 4), default caching
    // (input is the only thing we want resident in L2).
    int o[CHUNKS], ibase[CHUNKS], p[CHUNKS];
    float2 e[CHUNKS];
    #pragma unroll
    for (int c = 0; c < CHUNKS; c++) {
        o[c] = block_base + c * BLOCK + threadIdx.x;     // output float4 idx
        const int r = o[c] >> 17;                        // row (OUT_F4_PER_ROW = 2^17)
        p[c] = o[c] & (OUT_F4_PER_ROW - 1);              // position within row
        ibase[c] = r * L + 2 * p[c];                     // input float index
        e[c] = *reinterpret_cast<const float2*>(x + ibase[c]);
    }

    #pragma unroll
    for (int c = 0; c < CHUNKS; c++) {
        // Halo taps: left = x[2p-1], right = x[2p+2] (zero outside row).
        float left  = __shfl_up_sync(0xffffffffu, e[c].y, 1);
        float right = __shfl_down_sync(0xffffffffu, e[c].x, 1);
        if (lane == 0)
            left  = (p[c] == 0) ? 0.0f : __ldg(x + ibase[c] - 1);
        if (lane == 31)
            right = (p[c] == OUT_F4_PER_ROW - 1) ? 0.0f : __ldg(x + ibase[c] + 2);

        const float s01 = e[c].x + e[c].y;   // x[2p] + x[2p+1]
        float4 ov;
        ov.x = (left + s01)  > 0.5f ? 1.0f : 0.0f;    // out[4p]
        ov.y =  s01          > 0.5f ? 1.0f : 0.0f;    // out[4p+1]
        ov.z = (s01 + right) > 0.5f ? 1.0f : 0.0f;    // out[4p+2]
        ov.w = (e[c].y + right) > 0.5f ? 1.0f : 0.0f; // out[4p+3]

        __stwt(&out[o[c]], ov);   // write-through: no L2 allocation for output
    }
}

extern "C" void kernel_launch(void* const* d_in, const int* in_sizes, int n_in,
                              void* d_out, int out_size)
{
    const float* x = (const float*)d_in[0];
    float4* out = (float4*)d_out;

    const int total_out_f4 = (2 * in_sizes[0]) / 4;      // 8388608
    const int grid = total_out_f4 / (BLOCK * CHUNKS);    // 8192

    expand_mask_kernel<<<grid, BLOCK>>>(x, out);
}

// round 9
// speedup vs baseline: 1.0165x; 1.0165x over previous
#include <cuda_runtime.h>
#include <cstdint>

// ExpandMask: x [B=64, 1, L=262144] f32 -> out [B, 1, 2L] float (0.0/1.0)
//   out[2i]   = (x[i-1] + x[i] + x[i+1] > 0.5)   (zero taps outside row)
//   out[2i+1] = (x[i]   + x[i+1]        > 0.5)
//
// R9: R5 coalesced mapping + policies (dense LDG.64 loads .cs, dense STG.128
// stores .cs, shuffle halos, CHUNKS=4), but BLOCK=1024 so each block owns a
// 64KB contiguous output span (longer same-row DRAM write runs) and the grid
// shrinks to 2048 blocks (fewer waves; 2 blocks/SM -> 64 warps/SM).

static constexpr int L = 262144;                    // input row length
static constexpr int OUT_F4_PER_ROW = (2 * L) / 4;  // 131072 = 2^17
static constexpr int CHUNKS = 4;
static constexpr int BLOCK = 1024;

__global__ void __launch_bounds__(BLOCK) expand_mask_kernel(
    const float* __restrict__ x, float4* __restrict__ out)
{
    const int lane = threadIdx.x & 31;
    const int block_base = blockIdx.x * (BLOCK * CHUNKS);

    // Front-batch 4 independent dense float2 loads (MLP = 4).
    int o[CHUNKS], ibase[CHUNKS], p[CHUNKS];
    float2 e[CHUNKS];
    #pragma unroll
    for (int c = 0; c < CHUNKS; c++) {
        o[c] = block_base + c * BLOCK + threadIdx.x;     // output float4 idx
        const int r = o[c] >> 17;                        // row (OUT_F4_PER_ROW = 2^17)
        p[c] = o[c] & (OUT_F4_PER_ROW - 1);              // position within row
        ibase[c] = r * L + 2 * p[c];                     // input float index
        e[c] = __ldcs(reinterpret_cast<const float2*>(x + ibase[c]));
    }

    #pragma unroll
    for (int c = 0; c < CHUNKS; c++) {
        // Halo taps: left = x[2p-1], right = x[2p+2] (zero outside row).
        float left  = __shfl_up_sync(0xffffffffu, e[c].y, 1);
        float right = __shfl_down_sync(0xffffffffu, e[c].x, 1);
        if (lane == 0)
            left  = (p[c] == 0) ? 0.0f : __ldg(x + ibase[c] - 1);
        if (lane == 31)
            right = (p[c] == OUT_F4_PER_ROW - 1) ? 0.0f : __ldg(x + ibase[c] + 2);

        const float s01 = e[c].x + e[c].y;   // x[2p] + x[2p+1]
        float4 ov;
        ov.x = (left + s01)  > 0.5f ? 1.0f : 0.0f;    // out[4p]
        ov.y =  s01          > 0.5f ? 1.0f : 0.0f;    // out[4p+1]
        ov.z = (s01 + right) > 0.5f ? 1.0f : 0.0f;    // out[4p+2]
        ov.w = (e[c].y + right) > 0.5f ? 1.0f : 0.0f; // out[4p+3]

        __stcs(&out[o[c]], ov);   // evict-first: pure write stream
    }
}

extern "C" void kernel_launch(void* const* d_in, const int* in_sizes, int n_in,
                              void* d_out, int out_size)
{
    const float* x = (const float*)d_in[0];
    float4* out = (float4*)d_out;

    const int total_out_f4 = (2 * in_sizes[0]) / 4;      // 8388608
    const int grid = total_out_f4 / (BLOCK * CHUNKS);    // 2048

    expand_mask_kernel<<<grid, BLOCK>>>(x, out);
}